// round 10
// baseline (speedup 1.0000x reference)
#include <cuda_runtime.h>
#include <math.h>

#define Bn  128
#define NAn 8
#define ADn 16
#define DMn 512
#define DIn 1024
#define DSn 32
#define DRn 32
#define NBn 4
#define ODn 128
#define NBLK 128
#define NTHR 512

// ---------------- persistent scratch (no allocations allowed) ----------------
__device__ float g_x[Bn*DMn];
__device__ float g_ctx[Bn*DMn];
__device__ float g_xn[Bn*DMn];
__device__ float g_xc[Bn*DIn];
__device__ float g_sz[Bn*DIn];
__device__ float g_ys[Bn*DIn];
__device__ float g_aprev[Bn*ADn];
__device__ float g_part[4][Bn*DMn];
__device__ float g_dbcp[8][Bn*96];
__device__ float g_hist[8*4*Bn*DIn];
__device__ float g_negeA[8*DIn*DSn];
__device__ float g_h[(size_t)8*DSn*Bn*DIn];
__device__ unsigned g_barA;   // zero-init
__device__ unsigned g_barG;   // zero-init

__device__ __forceinline__ float sigmoidf_(float x){ return 1.f/(1.f+__expf(-x)); }
__device__ __forceinline__ float siluf_(float x){ return x*sigmoidf_(x); }
__device__ __forceinline__ float softplusf_(float x){ return (x>20.f)? x : log1pf(__expf(x)); }

// ---------------- software grid barrier (all NBLK blocks resident) ----------------
__device__ __forceinline__ void gridbar(){
  __syncthreads();
  if (threadIdx.x == 0){
    __threadfence();                               // publish this block's writes
    unsigned g = *((volatile unsigned*)&g_barG);
    if (atomicAdd(&g_barA, 1u) == NBLK-1u){
      *((volatile unsigned*)&g_barA) = 0u;
      __threadfence();
      *((volatile unsigned*)&g_barG) = g + 1u;     // release
    } else {
      while (*((volatile unsigned*)&g_barG) == g) {}
      __threadfence();                             // acquire
    }
  }
  __syncthreads();
}

// ---------------- block-wide LayerNorm stats over 512 values (1/thread) ----------------
__device__ __forceinline__ float2 blockLN(float x, float* red, int t){
  float s = x, q = x*x;
  #pragma unroll
  for (int o=16;o;o>>=1){ s+=__shfl_xor_sync(0xffffffffu,s,o); q+=__shfl_xor_sync(0xffffffffu,q,o); }
  if ((t&31)==0){ red[t>>5]=s; red[16+(t>>5)]=q; }
  __syncthreads();
  if (t==0){
    float S=0,Q=0;
    #pragma unroll
    for (int w=0;w<16;w++){ S+=red[w]; Q+=red[16+w]; }
    float m=S*(1.f/DMn);
    red[32]=m; red[33]=rsqrtf(Q*(1.f/DMn)-m*m+1e-5f);
  }
  __syncthreads();
  float2 r = make_float2(red[32], red[33]);
  __syncthreads();
  return r;
}

// ---------------- phase: embed + ctx + LN -> g_xn ----------------
__device__ __forceinline__ void phaseEmbed(float* sm, int bid, int t,
    const float* __restrict__ obs_rep, const float* __restrict__ obs,
    const float* __restrict__ We, const float* __restrict__ be,
    const float* __restrict__ Wo, const float* __restrict__ ln0, int i){
  float* sobs = sm;          // 128
  float* sap  = sm + 128;    // 16
  float* red  = sm + 160;    // 34
  int b = bid;
  if (t < ODn) sobs[t] = obs[(b*NAn+i)*ODn + t];
  if (i > 0 && t < ADn) sap[t] = __ldcg(&g_aprev[b*ADn + t]);
  __syncthreads();
  int c = t;
  float x = be[c];
  if (i > 0){
    #pragma unroll
    for (int a=0;a<ADn;a++) x += sap[a]*We[a*DMn + c];
  }
  float cv = obs_rep[(b*NAn+i)*DMn + c];
  #pragma unroll 4
  for (int o=0;o<ODn;o++) cv += sobs[o]*Wo[o*DMn + c];
  __stcg(&g_x[b*DMn + c], x);
  __stcg(&g_ctx[b*DMn + c], cv);
  float2 mr = blockLN(x, red, t);
  __stcg(&g_xn[b*DMn + c], (x-mr.x)*mr.y*ln0[c]);
}

// ---------------- phase A: xn[128,512]@Win[512,2048] + conv/silu epilogue ----------------
__device__ __forceinline__ void phaseA(float* sm, int bid, int t,
    const float* __restrict__ Win, const float* __restrict__ cw,
    const float* __restrict__ cb, int inst, int step){
  float* As = sm;          // [32][33]
  float* Bs = sm + 1056;   // [32][64]
  int m0 = (bid>>5)*32, n0 = (bid&31)*64;
  int ty = t>>5, tx = t&31;
  int lr = t>>4, lc2 = (t&15)*2, lc4 = (t&15)*4;
  float a0r, a1r; float4 b4r;
  { float2 av = __ldcg((const float2*)&g_xn[(m0+lr)*DMn + lc2]);
    a0r = av.x; a1r = av.y;
    b4r = *(const float4*)&Win[lr*(2*DIn) + n0 + lc4]; }
  float c00=0.f,c01=0.f,c10=0.f,c11=0.f;
  for (int kc=0; kc<DMn; kc+=32){
    As[lc2*33+lr]=a0r; As[(lc2+1)*33+lr]=a1r;
    *(float4*)&Bs[lr*64+lc4]=b4r;
    __syncthreads();
    if (kc+32 < DMn){
      float2 av = __ldcg((const float2*)&g_xn[(m0+lr)*DMn + kc+32 + lc2]);
      a0r = av.x; a1r = av.y;
      b4r = *(const float4*)&Win[(kc+32+lr)*(2*DIn) + n0 + lc4];
    }
    #pragma unroll
    for (int k=0;k<32;k++){
      float a0=As[k*33+ty], a1=As[k*33+ty+16];
      float2 bv = *(float2*)&Bs[k*64+tx*2];
      c00+=a0*bv.x; c01+=a0*bv.y; c10+=a1*bv.x; c11+=a1*bv.y;
    }
    __syncthreads();
  }
  int slot = step & 3;
  #pragma unroll
  for (int r=0;r<2;r++){
    int m = m0 + ty + 16*r;
    float v0 = r? c10 : c00;
    float v1 = r? c11 : c01;
    int n = n0 + tx*2;
    if (n0 < DIn){
      int d = n;
      __stcg((float2*)&g_hist[((inst*4+slot)*Bn + m)*DIn + d], make_float2(v0,v1));
      float2 w3 = *(const float2*)&cw[3*DIn+d];
      float2 cbv = *(const float2*)&cb[d];
      float cx = cbv.x + w3.x*v0, cy = cbv.y + w3.y*v1;
      if (step>=1){ float2 h1=__ldcg((const float2*)&g_hist[((inst*4+((step-1)&3))*Bn+m)*DIn+d]);
                    float2 w=*(const float2*)&cw[2*DIn+d]; cx+=w.x*h1.x; cy+=w.y*h1.y; }
      if (step>=2){ float2 h2=__ldcg((const float2*)&g_hist[((inst*4+((step-2)&3))*Bn+m)*DIn+d]);
                    float2 w=*(const float2*)&cw[1*DIn+d]; cx+=w.x*h2.x; cy+=w.y*h2.y; }
      if (step>=3){ float2 h3=__ldcg((const float2*)&g_hist[((inst*4+((step-3)&3))*Bn+m)*DIn+d]);
                    float2 w=*(const float2*)&cw[0*DIn+d]; cx+=w.x*h3.x; cy+=w.y*h3.y; }
      __stcg((float2*)&g_xc[m*DIn+d], make_float2(siluf_(cx), siluf_(cy)));
    } else {
      int d = n - DIn;
      __stcg((float2*)&g_sz[m*DIn+d], make_float2(siluf_(v0), siluf_(v1)));
    }
  }
}

// ---------------- phase B1: dbc partials, xc[128,1024]@Wx[1024,96], split-K=8 ----------------
__device__ __forceinline__ void phaseB1(float* sm, int bid, int t,
    const float* __restrict__ Wx){
  if (bid >= 32) return;
  float* As = sm;          // [32][33]
  float* Bs = sm + 1056;   // [32][96]
  int m0 = (bid>>3)*32, kz = bid&7, k0 = kz*128;
  int ty = t>>4, tx6 = (t&15)*6;
  int lr = t>>4, lc2 = (t&15)*2;
  float a0r, a1r; float2 w0r, w1r, w2r;
  { float2 av = __ldcg((const float2*)&g_xc[(m0+lr)*DIn + k0 + lc2]);
    a0r=av.x; a1r=av.y;
    const float* wb = &Wx[(k0+lr)*96 + tx6];
    w0r = *(const float2*)(wb+0); w1r = *(const float2*)(wb+2); w2r = *(const float2*)(wb+4); }
  float acc[6] = {0,0,0,0,0,0};
  for (int kc=0; kc<128; kc+=32){
    As[lc2*33+lr]=a0r; As[(lc2+1)*33+lr]=a1r;
    { float* bb = &Bs[lr*96 + tx6];
      *(float2*)(bb+0)=w0r; *(float2*)(bb+2)=w1r; *(float2*)(bb+4)=w2r; }
    __syncthreads();
    if (kc+32 < 128){
      float2 av = __ldcg((const float2*)&g_xc[(m0+lr)*DIn + k0 + kc+32 + lc2]);
      a0r=av.x; a1r=av.y;
      const float* wb = &Wx[(k0+kc+32+lr)*96 + tx6];
      w0r = *(const float2*)(wb+0); w1r = *(const float2*)(wb+2); w2r = *(const float2*)(wb+4);
    }
    #pragma unroll
    for (int k=0;k<32;k++){
      float a = As[k*33+ty];
      #pragma unroll
      for (int j=0;j<6;j++) acc[j] += a*Bs[k*96+tx6+j];
    }
    __syncthreads();
  }
  #pragma unroll
  for (int j=0;j<6;j++) __stcg(&g_dbcp[kz][(m0+ty)*96 + tx6 + j], acc[j]);
}

// ---------------- phase B2: reduce dbc -> delta -> SSM -> y*silu(z) ----------------
__device__ __forceinline__ void phaseB2(float* sm, int bid, int t,
    const float* __restrict__ Wdt, const float* __restrict__ dtb,
    const float* __restrict__ Dp, int inst, int step){
  float* sdbc = sm;          // [32][96]
  float* sWdt = sm + 3072;   // [32][32]
  float* snA  = sm + 4096;   // [32][32]
  int d0 = (bid&31)*32, b0 = (bid>>5)*32;
  #pragma unroll
  for (int u=0;u<2;u++){
    int e = t + 512*u;
    int r = e>>5, c = e&31;
    sWdt[r*32+c] = Wdt[r*DIn + d0 + c];
    snA[r*32+c]  = __ldcg(&g_negeA[inst*DIn*DSn + r*DIn + d0 + c]);
  }
  #pragma unroll
  for (int u=0;u<6;u++){
    int e = t + 512*u;
    int rr = e/96, cc = e - rr*96;
    float s = 0.f;
    #pragma unroll
    for (int p=0;p<8;p++) s += __ldcg(&g_dbcp[p][(b0+rr)*96 + cc]);
    sdbc[rr*96+cc] = s;
  }
  __syncthreads();
  int lane = t&31, br = t>>5;
  #pragma unroll
  for (int rep=0;rep<2;rep++){
    int brow = br + 16*rep;
    int b = b0 + brow, d = d0 + lane;
    float acc = dtb[d];
    #pragma unroll
    for (int r=0;r<DRn;r++) acc += sdbc[brow*96+r]*sWdt[r*32+lane];
    float delta = softplusf_(acc);
    float xc = __ldcg(&g_xc[b*DIn + d]);
    float dxc = delta*xc;
    float* hb = g_h + (size_t)inst*DSn*Bn*DIn + (size_t)b*DIn + d;
    float y = 0.f;
    #pragma unroll
    for (int s=0;s<DSn;s++){
      float dA = __expf(delta * snA[s*32+lane]);
      float hv = (step>0) ? __ldcg(&hb[(size_t)s*(Bn*DIn)]) : 0.f;
      hv = dA*hv + dxc*sdbc[brow*96+32+s];
      __stcg(&hb[(size_t)s*(Bn*DIn)], hv);
      y += hv*sdbc[brow*96+64+s];
    }
    y += Dp[d]*xc;
    __stcg(&g_ys[b*DIn + d], y*__ldcg(&g_sz[b*DIn + d]));
  }
}

// ---------------- phase D: ys[128,1024]@Wout[1024,512], split-K=4 partials ----------------
__device__ __forceinline__ void phaseD(float* sm, int bid, int t,
    const float* __restrict__ Wout){
  float* As = sm;          // [32][33]
  float* Bs = sm + 1056;   // [32][64]
  int n0 = (bid&7)*64, m0 = ((bid>>3)&3)*32, kz = bid>>5;
  int k0 = kz*256;
  int ty = t>>5, tx = t&31;
  int lr = t>>4, lc2 = (t&15)*2, lc4 = (t&15)*4;
  float a0r, a1r; float4 b4r;
  { float2 av = __ldcg((const float2*)&g_ys[(m0+lr)*DIn + k0 + lc2]);
    a0r=av.x; a1r=av.y;
    b4r = *(const float4*)&Wout[(k0+lr)*DMn + n0 + lc4]; }
  float c00=0.f,c01=0.f,c10=0.f,c11=0.f;
  for (int kc=0; kc<256; kc+=32){
    As[lc2*33+lr]=a0r; As[(lc2+1)*33+lr]=a1r;
    *(float4*)&Bs[lr*64+lc4]=b4r;
    __syncthreads();
    if (kc+32 < 256){
      float2 av = __ldcg((const float2*)&g_ys[(m0+lr)*DIn + k0 + kc+32 + lc2]);
      a0r=av.x; a1r=av.y;
      b4r = *(const float4*)&Wout[(k0+kc+32+lr)*DMn + n0 + lc4];
    }
    #pragma unroll
    for (int k=0;k<32;k++){
      float a0=As[k*33+ty], a1=As[k*33+ty+16];
      float2 bv = *(float2*)&Bs[k*64+tx*2];
      c00+=a0*bv.x; c01+=a0*bv.y; c10+=a1*bv.x; c11+=a1*bv.y;
    }
    __syncthreads();
  }
  float* P = g_part[kz];
  int n = n0 + tx*2;
  __stcg((float2*)&P[(m0+ty)*DMn + n],    make_float2(c00,c01));
  __stcg((float2*)&P[(m0+ty+16)*DMn + n], make_float2(c10,c11));
}

// ---------------- phase AddLN: x += sum partials; g_xn = LN(x)*lnw (+ctx) ----------------
__device__ __forceinline__ void phaseAddLN(float* sm, int bid, int t,
    const float* __restrict__ lnw, int useCtx){
  float* red = sm;   // 34
  int b = bid, c = t;
  float x = __ldcg(&g_x[b*DMn + c]);
  #pragma unroll
  for (int p=0;p<4;p++) x += __ldcg(&g_part[p][b*DMn + c]);
  __stcg(&g_x[b*DMn + c], x);
  float2 mr = blockLN(x, red, t);
  float xn = (x-mr.x)*mr.y*lnw[c];
  if (useCtx) xn += __ldcg(&g_ctx[b*DMn + c]);
  __stcg(&g_xn[b*DMn + c], xn);
}

// ---------------- phase Head: head GEMM + raw/act/logprob ----------------
__device__ __forceinline__ void phaseHead(float* sm, int bid, int t,
    const float* __restrict__ Wh, const float* __restrict__ lstd,
    const float* __restrict__ eps, float* __restrict__ out, int i){
  float* sxn   = sm;        // 512
  float* spart = sm + 512;  // 512
  int b = bid;
  sxn[t] = __ldcg(&g_xn[b*DMn + t]);
  __syncthreads();
  int seg = t>>4, j = t&15;
  float p = 0.f;
  #pragma unroll 4
  for (int k=seg*16; k<seg*16+16; k++) p += sxn[k]*Wh[k*ADn + j];
  spart[t] = p;
  __syncthreads();
  if (t < 16){
    float m = 0.f;
    #pragma unroll
    for (int sg=0;sg<32;sg++) m += spart[sg*16 + t];
    float std = softplusf_(lstd[t]);
    float e = eps[(b*NAn+i)*ADn + t];
    float raw = m + std*e;
    float act = tanhf(raw);
    int oidx = (b*NAn+i)*ADn + t;
    out[oidx] = act;
    out[17408 + oidx] = raw;
    __stcg(&g_aprev[b*ADn + t], act);
    float term = -0.5f*e*e - logf(std)
               - 2.f*(0.69314718055994531f - raw - softplusf_(-2.f*raw));
    #pragma unroll
    for (int o=8;o;o>>=1) term += __shfl_xor_sync(0xffffu, term, o);
    if (t==0) out[16384 + b*NAn + i] = term - 0.5f*ADn*1.8378770664093453f;
  }
  __syncthreads();
}

// ---------------- the megakernel ----------------
__global__ void __launch_bounds__(NTHR, 1) mega(
    const float* __restrict__ obs_rep, const float* __restrict__ obs,
    const float* __restrict__ eps,
    const float* __restrict__ We, const float* __restrict__ be,
    const float* __restrict__ Wo,
    const float* __restrict__ ln1, const float* __restrict__ ln2,
    const float* __restrict__ ln_out,
    const float* __restrict__ Wh, const float* __restrict__ lstd,
    const float* __restrict__ ip_s, const float* __restrict__ cw_s,
    const float* __restrict__ cb_s, const float* __restrict__ xp_s,
    const float* __restrict__ dt_s, const float* __restrict__ dtb_s,
    const float* __restrict__ al_s, const float* __restrict__ D_s,
    const float* __restrict__ op_s,
    const float* __restrict__ ip_c, const float* __restrict__ cw_c,
    const float* __restrict__ cb_c, const float* __restrict__ xp_c,
    const float* __restrict__ dt_c, const float* __restrict__ dtb_c,
    const float* __restrict__ al_c, const float* __restrict__ D_c,
    const float* __restrict__ op_c,
    float* __restrict__ out){
  __shared__ float sm[5248];
  int bid = blockIdx.x, t = threadIdx.x;

  // prep: -exp(A_log) transposed
  for (int idx = bid*NTHR + t; idx < 8*DIn*DSn; idx += NBLK*NTHR){
    int inst = idx >> 15;
    int e = idx & 32767;
    int d = e >> 5, s = e & 31;
    int v = inst & 1, nb = inst >> 1;
    const float* src = (v ? al_c : al_s) + nb*DIn*DSn;
    __stcg(&g_negeA[inst*DIn*DSn + s*DIn + d], -__expf(src[d*DSn + s]));
  }
  gridbar();

  for (int i=0;i<NAn;i++){
    phaseEmbed(sm, bid, t, obs_rep, obs, We, be, Wo, ln1, i);
    gridbar();
    for (int cell=0; cell<8; cell++){
      int nb = cell>>1, v = cell&1;
      const float* Win  = (v? ip_c : ip_s) + (size_t)nb*DMn*2*DIn;
      const float* cw   = (v? cw_c : cw_s) + nb*4*DIn;
      const float* cb   = (v? cb_c : cb_s) + nb*DIn;
      const float* Wx   = (v? xp_c : xp_s) + (size_t)nb*DIn*96;
      const float* Wdt  = (v? dt_c : dt_s) + nb*DRn*DIn;
      const float* dtb  = (v? dtb_c: dtb_s)+ nb*DIn;
      const float* Dp   = (v? D_c  : D_s)  + nb*DIn;
      const float* Wout = (v? op_c : op_s) + (size_t)nb*DIn*DMn;

      phaseA(sm, bid, t, Win, cw, cb, cell, i);
      gridbar();
      phaseB1(sm, bid, t, Wx);
      gridbar();
      phaseB2(sm, bid, t, Wdt, dtb, Dp, cell, i);
      gridbar();
      phaseD(sm, bid, t, Wout);
      gridbar();
      const float* lnw; int uc;
      if (v==0){ lnw = ln2 + nb*DMn; uc = 1; }
      else if (nb < NBn-1){ lnw = ln1 + (nb+1)*DMn; uc = 0; }
      else { lnw = ln_out; uc = 0; }
      phaseAddLN(sm, bid, t, lnw, uc);
      gridbar();
    }
    phaseHead(sm, bid, t, Wh, lstd, eps, out, i);
    gridbar();
  }
}

extern "C" void kernel_launch(void* const* d_in, const int* in_sizes, int n_in,
                              void* d_out, int out_size){
  (void)in_sizes; (void)n_in; (void)out_size;
  mega<<<NBLK, NTHR>>>(
    (const float*)d_in[0],  (const float*)d_in[1],  (const float*)d_in[2],
    (const float*)d_in[3],  (const float*)d_in[4],  (const float*)d_in[5],
    (const float*)d_in[6],  (const float*)d_in[7],  (const float*)d_in[8],
    (const float*)d_in[9],  (const float*)d_in[10],
    (const float*)d_in[11], (const float*)d_in[12], (const float*)d_in[13],
    (const float*)d_in[14], (const float*)d_in[15], (const float*)d_in[16],
    (const float*)d_in[17], (const float*)d_in[18], (const float*)d_in[19],
    (const float*)d_in[20], (const float*)d_in[21], (const float*)d_in[22],
    (const float*)d_in[23], (const float*)d_in[24], (const float*)d_in[25],
    (const float*)d_in[26], (const float*)d_in[27], (const float*)d_in[28],
    (float*)d_out);
}